// round 5
// baseline (speedup 1.0000x reference)
#include <cuda_runtime.h>
#include <cstddef>

#define N_NODES 100000
#define N_EDGES 1600000
#define DIM     128
#define DOUT    64

typedef unsigned long long u64;

// ---------------- scratch (device globals; no allocation allowed) ----------
__device__ __align__(16) float g_bufA[(size_t)N_NODES * DIM];   // 51.2 MB
__device__ __align__(16) float g_bufB[(size_t)N_NODES * DIM];   // 51.2 MB
__device__ float g_dinv[N_NODES];
__device__ int   g_deg[N_NODES];        // in-degree (without self loop)
__device__ int   g_rowstart[N_NODES];
__device__ int   g_cursor[N_NODES];
__device__ __align__(8) int2 g_csr_edge[N_EDGES];   // {src, norm bits}
__device__ int   g_total;               // range allocator counter

// ---------------- degree / normalization / CSR -----------------------------
__global__ void k_deg_zero() {
    int i = blockIdx.x * blockDim.x + threadIdx.x;
    if (i < N_NODES) g_deg[i] = 0;
    if (i == 0) g_total = 0;
}

__global__ void k_deg_count(const int* __restrict__ ei) {
    int e = blockIdx.x * blockDim.x + threadIdx.x;
    if (e < N_EDGES) atomicAdd(&g_deg[ei[N_EDGES + e]], 1);
}

// block-parallel range allocation: one atomicAdd per block; range ORDER is
// irrelevant (CSR fill order is already arbitrary). Also computes dinv.
__global__ void __launch_bounds__(1024) k_rowstart() {
    int i    = blockIdx.x * 1024 + threadIdx.x;
    int lane = threadIdx.x & 31;
    int wid  = threadIdx.x >> 5;
    int deg  = (i < N_NODES) ? g_deg[i] : 0;

    int v = deg;
#pragma unroll
    for (int off = 1; off < 32; off <<= 1) {
        int t = __shfl_up_sync(0xffffffffu, v, off);
        if (lane >= off) v += t;
    }

    __shared__ int wsum[32];
    __shared__ int base;
    if (lane == 31) wsum[wid] = v;
    __syncthreads();
    if (wid == 0) {
        int wv = wsum[lane];
#pragma unroll
        for (int off = 1; off < 32; off <<= 1) {
            int t = __shfl_up_sync(0xffffffffu, wv, off);
            if (lane >= off) wv += t;
        }
        wsum[lane] = wv;
        if (lane == 31) base = atomicAdd(&g_total, wv);
    }
    __syncthreads();

    int excl = base + (wid > 0 ? wsum[wid - 1] : 0) + v - deg;
    if (i < N_NODES) {
        g_rowstart[i] = excl;
        g_cursor[i]   = excl;
        g_dinv[i]     = rsqrtf((float)(deg + 1));   // +1 self loop
    }
}

__global__ void k_csr_fill(const int* __restrict__ ei) {
    int e = blockIdx.x * blockDim.x + threadIdx.x;
    if (e >= N_EDGES) return;
    int s = ei[e];
    int d = ei[N_EDGES + e];
    int pos = atomicAdd(&g_cursor[d], 1);
    g_csr_edge[pos] = make_int2(s, __float_as_int(g_dinv[s] * g_dinv[d]));
}

// ---------------- GEMM: Y[n,NCOL] = X[n,128] @ W[128,NCOL] (+bias) ---------
// 128-row blocks, 256 threads, thread tile TR rows x 8 cols, f32x2 FMAs.
template <int NCOL, bool BIAS>
__global__ void __launch_bounds__(256, 2) k_gemm(
    const float* __restrict__ X, const float* __restrict__ W,
    const float* __restrict__ bias, float* __restrict__ Y, int nrows)
{
    constexpr int R   = 128;
    constexpr int Kc  = 32;
    constexpr int XST = Kc + 1;          // 33: conflict-free broadcast LDS
    constexpr int CGc = NCOL / 8;        // 16 (NCOL=128) or 8 (NCOL=64)
    constexpr int RG  = 256 / CGc;       // 16 or 32
    constexpr int TR  = R / RG;          // 8 or 4

    __shared__ float Ws[Kc * NCOL];      // 16KB or 8KB
    __shared__ float Xs[R * XST];        // 16.5KB

    const int tid  = threadIdx.x;
    const int cg   = tid % CGc;
    const int rg   = tid / CGc;
    const int row0 = blockIdx.x * R;

    u64 acc[TR][4];
#pragma unroll
    for (int r = 0; r < TR; ++r)
#pragma unroll
        for (int c = 0; c < 4; ++c) acc[r][c] = 0ull;

    for (int kt = 0; kt < DIM / Kc; ++kt) {
        // W chunk (rows kt*Kc .. +Kc-1, contiguous)
        const float4* Wg = (const float4*)(W + (size_t)kt * Kc * NCOL);
#pragma unroll
        for (int i = tid; i < Kc * NCOL / 4; i += 256) ((float4*)Ws)[i] = Wg[i];

        // X chunk: 128 rows x 32 k. float4 coalesced loads, scalar stores.
#pragma unroll
        for (int i = tid; i < R * Kc / 4; i += 256) {   // 1024
            int r  = i >> 3;
            int kk = (i & 7) << 2;
            float4 v = make_float4(0.f, 0.f, 0.f, 0.f);
            if (row0 + r < nrows)
                v = ((const float4*)(X + (size_t)(row0 + r) * DIM + kt * Kc))[i & 7];
            float* xp = Xs + r * XST + kk;
            xp[0] = v.x; xp[1] = v.y; xp[2] = v.z; xp[3] = v.w;
        }
        __syncthreads();

#pragma unroll 8
        for (int k = 0; k < Kc; ++k) {
            const ulonglong2* wrow = (const ulonglong2*)(Ws + k * NCOL + cg * 8);
            ulonglong2 wa = wrow[0];
            ulonglong2 wb = wrow[1];
#pragma unroll
            for (int r = 0; r < TR; ++r) {
                unsigned xu = __float_as_uint(Xs[(rg * TR + r) * XST + k]);
                u64 xp;
                asm("mov.b64 %0, {%1, %1};" : "=l"(xp) : "r"(xu));
                asm("fma.rn.f32x2 %0, %1, %2, %0;" : "+l"(acc[r][0]) : "l"(xp), "l"(wa.x));
                asm("fma.rn.f32x2 %0, %1, %2, %0;" : "+l"(acc[r][1]) : "l"(xp), "l"(wa.y));
                asm("fma.rn.f32x2 %0, %1, %2, %0;" : "+l"(acc[r][2]) : "l"(xp), "l"(wb.x));
                asm("fma.rn.f32x2 %0, %1, %2, %0;" : "+l"(acc[r][3]) : "l"(xp), "l"(wb.y));
            }
        }
        __syncthreads();
    }

#pragma unroll
    for (int r = 0; r < TR; ++r) {
        int row = row0 + rg * TR + r;
        if (row < nrows) {
            float f[8];
#pragma unroll
            for (int c = 0; c < 4; ++c)
                asm("mov.b64 {%0, %1}, %2;" : "=f"(f[2*c]), "=f"(f[2*c+1]) : "l"(acc[r][c]));
            if (BIAS) {
                const float* bp = bias + cg * 8;
#pragma unroll
                for (int c = 0; c < 8; ++c) f[c] += bp[c];
            }
            float4* yp = (float4*)(Y + (size_t)row * NCOL + cg * 8);
            yp[0] = make_float4(f[0], f[1], f[2], f[3]);
            yp[1] = make_float4(f[4], f[5], f[6], f[7]);
        }
    }
}

// ---------------- CSR aggregation + self-loop + bias + relu ----------------
// warp per node, register accumulation, single write; no atomics.
__global__ void __launch_bounds__(256) k_aggregate(
    const float* __restrict__ A, float* __restrict__ B,
    const float* __restrict__ bias)
{
    int node = (blockIdx.x * 256 + threadIdx.x) >> 5;
    int lane = threadIdx.x & 31;
    if (node >= N_NODES) return;

    const float4* A4 = (const float4*)A;
    int beg = g_rowstart[node];
    int cnt = g_deg[node];

    float4 ac0 = make_float4(0.f, 0.f, 0.f, 0.f);
    float4 ac1 = make_float4(0.f, 0.f, 0.f, 0.f);
    float4 ac2 = make_float4(0.f, 0.f, 0.f, 0.f);
    float4 ac3 = make_float4(0.f, 0.f, 0.f, 0.f);

    int j = 0;
    for (; j + 4 <= cnt; j += 4) {
        int2 e0 = g_csr_edge[beg + j + 0];
        int2 e1 = g_csr_edge[beg + j + 1];
        int2 e2 = g_csr_edge[beg + j + 2];
        int2 e3 = g_csr_edge[beg + j + 3];
        float4 v0 = A4[(size_t)e0.x * 32 + lane];
        float4 v1 = A4[(size_t)e1.x * 32 + lane];
        float4 v2 = A4[(size_t)e2.x * 32 + lane];
        float4 v3 = A4[(size_t)e3.x * 32 + lane];
        float n0 = __int_as_float(e0.y), n1 = __int_as_float(e1.y);
        float n2 = __int_as_float(e2.y), n3 = __int_as_float(e3.y);
        ac0.x += v0.x * n0; ac0.y += v0.y * n0; ac0.z += v0.z * n0; ac0.w += v0.w * n0;
        ac1.x += v1.x * n1; ac1.y += v1.y * n1; ac1.z += v1.z * n1; ac1.w += v1.w * n1;
        ac2.x += v2.x * n2; ac2.y += v2.y * n2; ac2.z += v2.z * n2; ac2.w += v2.w * n2;
        ac3.x += v3.x * n3; ac3.y += v3.y * n3; ac3.z += v3.z * n3; ac3.w += v3.w * n3;
    }
    for (; j < cnt; ++j) {
        int2 e0 = g_csr_edge[beg + j];
        float n0 = __int_as_float(e0.y);
        float4 v0 = A4[(size_t)e0.x * 32 + lane];
        ac0.x += v0.x * n0; ac0.y += v0.y * n0; ac0.z += v0.z * n0; ac0.w += v0.w * n0;
    }

    float di = g_dinv[node];
    float sn = di * di;
    float4 self = A4[(size_t)node * 32 + lane];
    float4 bb   = ((const float4*)bias)[lane];
    float4 o;
    o.x = fmaxf((ac0.x + ac1.x) + (ac2.x + ac3.x) + self.x * sn + bb.x, 0.f);
    o.y = fmaxf((ac0.y + ac1.y) + (ac2.y + ac3.y) + self.y * sn + bb.y, 0.f);
    o.z = fmaxf((ac0.z + ac1.z) + (ac2.z + ac3.z) + self.z * sn + bb.z, 0.f);
    o.w = fmaxf((ac0.w + ac1.w) + (ac2.w + ac3.w) + self.w * sn + bb.w, 0.f);
    ((float4*)(B + (size_t)node * DIM))[lane] = o;
}

// ---------------- launch ----------------------------------------------------
extern "C" void kernel_launch(void* const* d_in, const int* in_sizes, int n_in,
                              void* d_out, int out_size)
{
    const float* x    = (const float*)d_in[0];
    const int*   ei   = (const int*)d_in[1];     // int32 (JAX x64 disabled)
    const float* W1   = (const float*)d_in[2];
    const float* b1   = (const float*)d_in[3];
    const float* W2   = (const float*)d_in[4];
    const float* b2   = (const float*)d_in[5];
    const float* fcW  = (const float*)d_in[6];
    const float* fcb  = (const float*)d_in[7];
    float*       out  = (float*)d_out;

    void *pA_, *pB_;
    cudaGetSymbolAddress(&pA_, g_bufA);
    cudaGetSymbolAddress(&pB_, g_bufB);
    float* bufA = (float*)pA_;
    float* bufB = (float*)pB_;

    const int TB = 256;
    const int gN  = (N_NODES + TB - 1) / TB;
    const int gE  = (N_EDGES + TB - 1) / TB;
    const int gG  = (N_NODES + 127) / 128;          // 128-row gemm tiles
    const int gAg = (N_NODES * 32 + TB - 1) / TB;   // warp per node
    const int gRS = (N_NODES + 1023) / 1024;

    // CSR precompute
    k_deg_zero<<<gN, TB>>>();
    k_deg_count<<<gE, TB>>>(ei);
    k_rowstart<<<gRS, 1024>>>();
    k_csr_fill<<<gE, TB>>>(ei);

    // layer 1
    k_gemm<DIM, false><<<gG, TB>>>(x, W1, nullptr, bufA, N_NODES);
    k_aggregate<<<gAg, TB>>>(bufA, bufB, b1);

    // layer 2
    k_gemm<DIM, false><<<gG, TB>>>(bufB, W2, nullptr, bufA, N_NODES);
    k_aggregate<<<gAg, TB>>>(bufA, bufB, b2);

    // fc
    k_gemm<DOUT, true><<<gG, TB>>>(bufB, fcW, fcb, out, N_NODES);
}

// round 6
// speedup vs baseline: 1.0318x; 1.0318x over previous
#include <cuda_runtime.h>
#include <cstddef>

#define N_NODES 100000
#define N_EDGES 1600000
#define DIM     128
#define DOUT    64

typedef unsigned long long u64;

// ---------------- scratch (device globals; no allocation allowed) ----------
__device__ __align__(16) float g_bufA[(size_t)N_NODES * DIM];   // 51.2 MB
__device__ __align__(16) float g_bufB[(size_t)N_NODES * DIM];   // 51.2 MB
__device__ float g_dinv[N_NODES];
__device__ int   g_deg[N_NODES];        // in-degree (without self loop)
__device__ int   g_rowstart[N_NODES];
__device__ int   g_cursor[N_NODES];
__device__ __align__(8) int2 g_csr_edge[N_EDGES];   // {src, norm bits}
__device__ int   g_total;               // range allocator counter

// ---------------- degree / normalization / CSR -----------------------------
__global__ void k_deg_zero() {
    int i = blockIdx.x * blockDim.x + threadIdx.x;
    if (i < N_NODES) g_deg[i] = 0;
    if (i == 0) g_total = 0;
}

__global__ void k_deg_count(const int* __restrict__ ei) {
    int e = blockIdx.x * blockDim.x + threadIdx.x;
    if (e < N_EDGES) atomicAdd(&g_deg[ei[N_EDGES + e]], 1);
}

// block-parallel range allocation: one atomicAdd per block; range ORDER is
// irrelevant (CSR fill order is already arbitrary). Also computes dinv.
__global__ void __launch_bounds__(1024) k_rowstart() {
    int i    = blockIdx.x * 1024 + threadIdx.x;
    int lane = threadIdx.x & 31;
    int wid  = threadIdx.x >> 5;
    int deg  = (i < N_NODES) ? g_deg[i] : 0;

    int v = deg;
#pragma unroll
    for (int off = 1; off < 32; off <<= 1) {
        int t = __shfl_up_sync(0xffffffffu, v, off);
        if (lane >= off) v += t;
    }

    __shared__ int wsum[32];
    __shared__ int base;
    if (lane == 31) wsum[wid] = v;
    __syncthreads();
    if (wid == 0) {
        int wv = wsum[lane];
#pragma unroll
        for (int off = 1; off < 32; off <<= 1) {
            int t = __shfl_up_sync(0xffffffffu, wv, off);
            if (lane >= off) wv += t;
        }
        wsum[lane] = wv;
        if (lane == 31) base = atomicAdd(&g_total, wv);
    }
    __syncthreads();

    int excl = base + (wid > 0 ? wsum[wid - 1] : 0) + v - deg;
    if (i < N_NODES) {
        g_rowstart[i] = excl;
        g_cursor[i]   = excl;
        g_dinv[i]     = rsqrtf((float)(deg + 1));   // +1 self loop
    }
}

__global__ void k_csr_fill(const int* __restrict__ ei) {
    int e = blockIdx.x * blockDim.x + threadIdx.x;
    if (e >= N_EDGES) return;
    int s = ei[e];
    int d = ei[N_EDGES + e];
    int pos = atomicAdd(&g_cursor[d], 1);
    g_csr_edge[pos] = make_int2(s, __float_as_int(g_dinv[s] * g_dinv[d]));
}

// ---------------- GEMM: Y[n,NCOL] = X[n,128] @ W[128,NCOL] (+bias) ---------
// R4 design (proven): 32-row blocks, 256 threads, 4x4 thread tile, f32x2 FMAs.
// fma pipe is the binder (8 FFMA2 @ rt 2 = 16 SMSP-cyc per warp-k); LDS+MOV
// fit underneath. Do not re-tile without tensor cores.
template <int NCOL, bool BIAS>
__global__ void __launch_bounds__(256) k_gemm(
    const float* __restrict__ X, const float* __restrict__ W,
    const float* __restrict__ bias, float* __restrict__ Y, int nrows)
{
    constexpr int CG  = NCOL / 4;     // float4 column groups (32 or 16)
    constexpr int RG  = 256 / CG;     // row groups (8 or 16)
    constexpr int RPT = 32 / RG;      // rows per thread (4 or 2)

    __shared__ float Ws[64 * NCOL];
    __shared__ float Xs[32 * 68];

    const int tid  = threadIdx.x;
    const int cg   = tid % CG;
    const int rg   = tid / CG;
    const int row0 = blockIdx.x * 32;

    u64 accL[RPT], accH[RPT];
#pragma unroll
    for (int r = 0; r < RPT; ++r) { accL[r] = 0ull; accH[r] = 0ull; }

    for (int kt = 0; kt < 2; ++kt) {
        const float4* Wg  = (const float4*)(W + (size_t)kt * 64 * NCOL);
        float4*       Ws4 = (float4*)Ws;
#pragma unroll 4
        for (int i = tid; i < 64 * NCOL / 4; i += 256) Ws4[i] = Wg[i];

        for (int i = tid; i < 32 * 16; i += 256) {
            int r  = i / 16;
            int kk = i % 16;
            float4 v = make_float4(0.f, 0.f, 0.f, 0.f);
            if (row0 + r < nrows)
                v = ((const float4*)(X + (size_t)(row0 + r) * DIM + kt * 64))[kk];
            ((float4*)(Xs + r * 68))[kk] = v;
        }
        __syncthreads();

#pragma unroll 8
        for (int k = 0; k < 64; ++k) {
            ulonglong2 w = *((const ulonglong2*)(Ws + k * NCOL) + cg);
#pragma unroll
            for (int r = 0; r < RPT; ++r) {
                unsigned xu = __float_as_uint(Xs[(rg * RPT + r) * 68 + k]);
                u64 xp;
                asm("mov.b64 %0, {%1, %1};" : "=l"(xp) : "r"(xu));
                asm("fma.rn.f32x2 %0, %1, %2, %0;" : "+l"(accL[r]) : "l"(xp), "l"(w.x));
                asm("fma.rn.f32x2 %0, %1, %2, %0;" : "+l"(accH[r]) : "l"(xp), "l"(w.y));
            }
        }
        __syncthreads();
    }

#pragma unroll
    for (int r = 0; r < RPT; ++r) {
        int row = row0 + rg * RPT + r;
        if (row < nrows) {
            float2 lo, hi;
            asm("mov.b64 {%0, %1}, %2;" : "=f"(lo.x), "=f"(lo.y) : "l"(accL[r]));
            asm("mov.b64 {%0, %1}, %2;" : "=f"(hi.x), "=f"(hi.y) : "l"(accH[r]));
            float4 o = make_float4(lo.x, lo.y, hi.x, hi.y);
            if (BIAS) {
                float4 b = ((const float4*)bias)[cg];
                o.x += b.x; o.y += b.y; o.z += b.z; o.w += b.w;
            }
            ((float4*)(Y + (size_t)row * NCOL))[cg] = o;
        }
    }
}

// ---------------- CSR aggregation + self-loop + bias + relu ----------------
// warp per node, register accumulation, single write; no atomics.
__global__ void __launch_bounds__(256) k_aggregate(
    const float* __restrict__ A, float* __restrict__ B,
    const float* __restrict__ bias)
{
    int node = (blockIdx.x * 256 + threadIdx.x) >> 5;
    int lane = threadIdx.x & 31;
    if (node >= N_NODES) return;

    const float4* A4 = (const float4*)A;
    int beg = g_rowstart[node];
    int cnt = g_deg[node];

    float4 ac0 = make_float4(0.f, 0.f, 0.f, 0.f);
    float4 ac1 = make_float4(0.f, 0.f, 0.f, 0.f);
    float4 ac2 = make_float4(0.f, 0.f, 0.f, 0.f);
    float4 ac3 = make_float4(0.f, 0.f, 0.f, 0.f);

    int j = 0;
    for (; j + 4 <= cnt; j += 4) {
        int2 e0 = g_csr_edge[beg + j + 0];
        int2 e1 = g_csr_edge[beg + j + 1];
        int2 e2 = g_csr_edge[beg + j + 2];
        int2 e3 = g_csr_edge[beg + j + 3];
        float4 v0 = A4[(size_t)e0.x * 32 + lane];
        float4 v1 = A4[(size_t)e1.x * 32 + lane];
        float4 v2 = A4[(size_t)e2.x * 32 + lane];
        float4 v3 = A4[(size_t)e3.x * 32 + lane];
        float n0 = __int_as_float(e0.y), n1 = __int_as_float(e1.y);
        float n2 = __int_as_float(e2.y), n3 = __int_as_float(e3.y);
        ac0.x += v0.x * n0; ac0.y += v0.y * n0; ac0.z += v0.z * n0; ac0.w += v0.w * n0;
        ac1.x += v1.x * n1; ac1.y += v1.y * n1; ac1.z += v1.z * n1; ac1.w += v1.w * n1;
        ac2.x += v2.x * n2; ac2.y += v2.y * n2; ac2.z += v2.z * n2; ac2.w += v2.w * n2;
        ac3.x += v3.x * n3; ac3.y += v3.y * n3; ac3.z += v3.z * n3; ac3.w += v3.w * n3;
    }
    for (; j < cnt; ++j) {
        int2 e0 = g_csr_edge[beg + j];
        float n0 = __int_as_float(e0.y);
        float4 v0 = A4[(size_t)e0.x * 32 + lane];
        ac0.x += v0.x * n0; ac0.y += v0.y * n0; ac0.z += v0.z * n0; ac0.w += v0.w * n0;
    }

    float di = g_dinv[node];
    float sn = di * di;
    float4 self = A4[(size_t)node * 32 + lane];
    float4 bb   = ((const float4*)bias)[lane];
    float4 o;
    o.x = fmaxf((ac0.x + ac1.x) + (ac2.x + ac3.x) + self.x * sn + bb.x, 0.f);
    o.y = fmaxf((ac0.y + ac1.y) + (ac2.y + ac3.y) + self.y * sn + bb.y, 0.f);
    o.z = fmaxf((ac0.z + ac1.z) + (ac2.z + ac3.z) + self.z * sn + bb.z, 0.f);
    o.w = fmaxf((ac0.w + ac1.w) + (ac2.w + ac3.w) + self.w * sn + bb.w, 0.f);
    ((float4*)(B + (size_t)node * DIM))[lane] = o;
}

// ---------------- launch ----------------------------------------------------
extern "C" void kernel_launch(void* const* d_in, const int* in_sizes, int n_in,
                              void* d_out, int out_size)
{
    const float* x    = (const float*)d_in[0];
    const int*   ei   = (const int*)d_in[1];     // int32 (JAX x64 disabled)
    const float* W1   = (const float*)d_in[2];
    const float* b1   = (const float*)d_in[3];
    const float* W2   = (const float*)d_in[4];
    const float* b2   = (const float*)d_in[5];
    const float* fcW  = (const float*)d_in[6];
    const float* fcb  = (const float*)d_in[7];
    float*       out  = (float*)d_out;

    void *pA_, *pB_;
    cudaGetSymbolAddress(&pA_, g_bufA);
    cudaGetSymbolAddress(&pB_, g_bufB);
    float* bufA = (float*)pA_;
    float* bufB = (float*)pB_;

    const int TB = 256;
    const int gN  = (N_NODES + TB - 1) / TB;
    const int gE  = (N_EDGES + TB - 1) / TB;
    const int gG  = (N_NODES + 31) / 32;            // 32-row gemm tiles
    const int gAg = (N_NODES * 32 + TB - 1) / TB;   // warp per node
    const int gRS = (N_NODES + 1023) / 1024;

    // CSR precompute
    k_deg_zero<<<gN, TB>>>();
    k_deg_count<<<gE, TB>>>(ei);
    k_rowstart<<<gRS, 1024>>>();
    k_csr_fill<<<gE, TB>>>(ei);

    // layer 1
    k_gemm<DIM, false><<<gG, TB>>>(x, W1, nullptr, bufA, N_NODES);
    k_aggregate<<<gAg, TB>>>(bufA, bufB, b1);

    // layer 2
    k_gemm<DIM, false><<<gG, TB>>>(bufB, W2, nullptr, bufA, N_NODES);
    k_aggregate<<<gAg, TB>>>(bufA, bufB, b2);

    // fc
    k_gemm<DOUT, true><<<gG, TB>>>(bufB, fcW, fcb, out, N_NODES);
}

// round 7
// speedup vs baseline: 1.0528x; 1.0204x over previous
#include <cuda_runtime.h>
#include <cstddef>

#define N_NODES 100000
#define N_EDGES 1600000
#define DIM     128
#define DOUT    64

typedef unsigned long long u64;

// ---------------- scratch (device globals; no allocation allowed) ----------
__device__ __align__(16) float g_bufA[(size_t)N_NODES * DIM];   // 51.2 MB
__device__ __align__(16) float g_bufB[(size_t)N_NODES * DIM];   // 51.2 MB
__device__ float g_dinv[N_NODES];
__device__ int   g_deg[N_NODES];        // in-degree (without self loop)
__device__ int   g_rowstart[N_NODES];
__device__ int   g_cursor[N_NODES];
__device__ __align__(8) int2 g_csr_edge[N_EDGES];   // {src, norm bits}
__device__ int   g_total;               // range allocator counter

// ---------------- degree / normalization / CSR -----------------------------
__global__ void k_deg_zero() {
    int i = blockIdx.x * blockDim.x + threadIdx.x;
    if (i < N_NODES) g_deg[i] = 0;
    if (i == 0) g_total = 0;
}

__global__ void k_deg_count(const int* __restrict__ ei) {
    int e = blockIdx.x * blockDim.x + threadIdx.x;
    if (e < N_EDGES) atomicAdd(&g_deg[ei[N_EDGES + e]], 1);
}

// block-parallel range allocation: one atomicAdd per block; range ORDER is
// irrelevant (CSR fill order is already arbitrary). Also computes dinv.
__global__ void __launch_bounds__(1024) k_rowstart() {
    int i    = blockIdx.x * 1024 + threadIdx.x;
    int lane = threadIdx.x & 31;
    int wid  = threadIdx.x >> 5;
    int deg  = (i < N_NODES) ? g_deg[i] : 0;

    int v = deg;
#pragma unroll
    for (int off = 1; off < 32; off <<= 1) {
        int t = __shfl_up_sync(0xffffffffu, v, off);
        if (lane >= off) v += t;
    }

    __shared__ int wsum[32];
    __shared__ int base;
    if (lane == 31) wsum[wid] = v;
    __syncthreads();
    if (wid == 0) {
        int wv = wsum[lane];
#pragma unroll
        for (int off = 1; off < 32; off <<= 1) {
            int t = __shfl_up_sync(0xffffffffu, wv, off);
            if (lane >= off) wv += t;
        }
        wsum[lane] = wv;
        if (lane == 31) base = atomicAdd(&g_total, wv);
    }
    __syncthreads();

    int excl = base + (wid > 0 ? wsum[wid - 1] : 0) + v - deg;
    if (i < N_NODES) {
        g_rowstart[i] = excl;
        g_cursor[i]   = excl;
        g_dinv[i]     = rsqrtf((float)(deg + 1));   // +1 self loop
    }
}

__global__ void k_csr_fill(const int* __restrict__ ei) {
    int e = blockIdx.x * blockDim.x + threadIdx.x;
    if (e >= N_EDGES) return;
    int s = ei[e];
    int d = ei[N_EDGES + e];
    int pos = atomicAdd(&g_cursor[d], 1);
    g_csr_edge[pos] = make_int2(s, __float_as_int(g_dinv[s] * g_dinv[d]));
}

// ---------------- GEMM: Y[n,NCOL] = X[n,128] @ W[128,NCOL] (+bias) ---------
// R4 design (proven): 32-row blocks, 256 threads, 4x4 thread tile, f32x2 FMAs.
// fma pipe is the binder (8 FFMA2 @ rt 2 = 16 SMSP-cyc per warp-k); LDS+MOV
// fit underneath. Do not re-tile without tensor cores.
template <int NCOL, bool BIAS>
__global__ void __launch_bounds__(256) k_gemm(
    const float* __restrict__ X, const float* __restrict__ W,
    const float* __restrict__ bias, float* __restrict__ Y, int nrows)
{
    constexpr int CG  = NCOL / 4;     // float4 column groups (32 or 16)
    constexpr int RG  = 256 / CG;     // row groups (8 or 16)
    constexpr int RPT = 32 / RG;      // rows per thread (4 or 2)

    __shared__ float Ws[64 * NCOL];
    __shared__ float Xs[32 * 68];

    const int tid  = threadIdx.x;
    const int cg   = tid % CG;
    const int rg   = tid / CG;
    const int row0 = blockIdx.x * 32;

    u64 accL[RPT], accH[RPT];
#pragma unroll
    for (int r = 0; r < RPT; ++r) { accL[r] = 0ull; accH[r] = 0ull; }

    for (int kt = 0; kt < 2; ++kt) {
        const float4* Wg  = (const float4*)(W + (size_t)kt * 64 * NCOL);
        float4*       Ws4 = (float4*)Ws;
#pragma unroll 4
        for (int i = tid; i < 64 * NCOL / 4; i += 256) Ws4[i] = Wg[i];

        for (int i = tid; i < 32 * 16; i += 256) {
            int r  = i / 16;
            int kk = i % 16;
            float4 v = make_float4(0.f, 0.f, 0.f, 0.f);
            if (row0 + r < nrows)
                v = ((const float4*)(X + (size_t)(row0 + r) * DIM + kt * 64))[kk];
            ((float4*)(Xs + r * 68))[kk] = v;
        }
        __syncthreads();

#pragma unroll 8
        for (int k = 0; k < 64; ++k) {
            ulonglong2 w = *((const ulonglong2*)(Ws + k * NCOL) + cg);
#pragma unroll
            for (int r = 0; r < RPT; ++r) {
                unsigned xu = __float_as_uint(Xs[(rg * RPT + r) * 68 + k]);
                u64 xp;
                asm("mov.b64 %0, {%1, %1};" : "=l"(xp) : "r"(xu));
                asm("fma.rn.f32x2 %0, %1, %2, %0;" : "+l"(accL[r]) : "l"(xp), "l"(w.x));
                asm("fma.rn.f32x2 %0, %1, %2, %0;" : "+l"(accH[r]) : "l"(xp), "l"(w.y));
            }
        }
        __syncthreads();
    }

#pragma unroll
    for (int r = 0; r < RPT; ++r) {
        int row = row0 + rg * RPT + r;
        if (row < nrows) {
            float2 lo, hi;
            asm("mov.b64 {%0, %1}, %2;" : "=f"(lo.x), "=f"(lo.y) : "l"(accL[r]));
            asm("mov.b64 {%0, %1}, %2;" : "=f"(hi.x), "=f"(hi.y) : "l"(accH[r]));
            float4 o = make_float4(lo.x, lo.y, hi.x, hi.y);
            if (BIAS) {
                float4 b = ((const float4*)bias)[cg];
                o.x += b.x; o.y += b.y; o.z += b.z; o.w += b.w;
            }
            ((float4*)(Y + (size_t)row * NCOL))[cg] = o;
        }
    }
}

// ---------------- CSR aggregation + self-loop + bias + relu ----------------
// warp per node, register accumulation, single write; no atomics.
// 2x unroll ONLY: 4x unroll overflows the L1tex wavefront queue at occ~8
// (cross-CTA spread, measured +30us in R6). Do not widen.
__global__ void __launch_bounds__(256) k_aggregate(
    const float* __restrict__ A, float* __restrict__ B,
    const float* __restrict__ bias)
{
    int node = (blockIdx.x * 256 + threadIdx.x) >> 5;
    int lane = threadIdx.x & 31;
    if (node >= N_NODES) return;

    const float4* A4 = (const float4*)A;
    int beg = g_rowstart[node];
    int cnt = g_deg[node];

    float4 acc0 = make_float4(0.f, 0.f, 0.f, 0.f);
    float4 acc1 = make_float4(0.f, 0.f, 0.f, 0.f);

    int j = 0;
    for (; j + 2 <= cnt; j += 2) {
        int2 e0 = g_csr_edge[beg + j];
        int2 e1 = g_csr_edge[beg + j + 1];
        float n0 = __int_as_float(e0.y);
        float n1 = __int_as_float(e1.y);
        float4 v0 = A4[(size_t)e0.x * 32 + lane];
        float4 v1 = A4[(size_t)e1.x * 32 + lane];
        acc0.x += v0.x * n0; acc0.y += v0.y * n0;
        acc0.z += v0.z * n0; acc0.w += v0.w * n0;
        acc1.x += v1.x * n1; acc1.y += v1.y * n1;
        acc1.z += v1.z * n1; acc1.w += v1.w * n1;
    }
    if (j < cnt) {
        int2 e0 = g_csr_edge[beg + j];
        float n0 = __int_as_float(e0.y);
        float4 v0 = A4[(size_t)e0.x * 32 + lane];
        acc0.x += v0.x * n0; acc0.y += v0.y * n0;
        acc0.z += v0.z * n0; acc0.w += v0.w * n0;
    }

    float di = g_dinv[node];
    float sn = di * di;
    float4 self = A4[(size_t)node * 32 + lane];
    float4 bb   = ((const float4*)bias)[lane];
    float4 o;
    o.x = fmaxf(acc0.x + acc1.x + self.x * sn + bb.x, 0.f);
    o.y = fmaxf(acc0.y + acc1.y + self.y * sn + bb.y, 0.f);
    o.z = fmaxf(acc0.z + acc1.z + self.z * sn + bb.z, 0.f);
    o.w = fmaxf(acc0.w + acc1.w + self.w * sn + bb.w, 0.f);
    ((float4*)(B + (size_t)node * DIM))[lane] = o;
}

// ---------------- launch ----------------------------------------------------
extern "C" void kernel_launch(void* const* d_in, const int* in_sizes, int n_in,
                              void* d_out, int out_size)
{
    const float* x    = (const float*)d_in[0];
    const int*   ei   = (const int*)d_in[1];     // int32 (JAX x64 disabled)
    const float* W1   = (const float*)d_in[2];
    const float* b1   = (const float*)d_in[3];
    const float* W2   = (const float*)d_in[4];
    const float* b2   = (const float*)d_in[5];
    const float* fcW  = (const float*)d_in[6];
    const float* fcb  = (const float*)d_in[7];
    float*       out  = (float*)d_out;

    void *pA_, *pB_;
    cudaGetSymbolAddress(&pA_, g_bufA);
    cudaGetSymbolAddress(&pB_, g_bufB);
    float* bufA = (float*)pA_;
    float* bufB = (float*)pB_;

    const int TB = 256;
    const int gN  = (N_NODES + TB - 1) / TB;
    const int gE  = (N_EDGES + TB - 1) / TB;
    const int gG  = (N_NODES + 31) / 32;            // 32-row gemm tiles
    const int gAg = (N_NODES * 32 + TB - 1) / TB;   // warp per node
    const int gRS = (N_NODES + 1023) / 1024;

    // CSR precompute
    k_deg_zero<<<gN, TB>>>();
    k_deg_count<<<gE, TB>>>(ei);
    k_rowstart<<<gRS, 1024>>>();
    k_csr_fill<<<gE, TB>>>(ei);

    // layer 1
    k_gemm<DIM, false><<<gG, TB>>>(x, W1, nullptr, bufA, N_NODES);
    k_aggregate<<<gAg, TB>>>(bufA, bufB, b1);

    // layer 2
    k_gemm<DIM, false><<<gG, TB>>>(bufB, W2, nullptr, bufA, N_NODES);
    k_aggregate<<<gAg, TB>>>(bufA, bufB, b2);

    // fc
    k_gemm<DOUT, true><<<gG, TB>>>(bufB, fcW, fcb, out, N_NODES);
}

// round 9
// speedup vs baseline: 1.1197x; 1.0635x over previous
#include <cuda_runtime.h>
#include <cuda_fp16.h>
#include <cstddef>
#include <cstdint>

#define N_NODES 100000
#define N_EDGES 1600000
#define DIM     128
#define DOUT    64

typedef unsigned long long u64;

// ---------------- scratch (device globals; no allocation allowed) ----------
__device__ __align__(16) float  g_bufA[(size_t)N_NODES * DIM];   // 51.2 MB
__device__ __align__(16) float  g_bufB[(size_t)N_NODES * DIM];   // 51.2 MB
__device__ __align__(16) __half g_bufH[(size_t)N_NODES * DIM];   // 25.6 MB (fp16 msgs)
__device__ float g_dinv[N_NODES];
__device__ int   g_deg[N_NODES];
__device__ int   g_rowstart[N_NODES];
__device__ int   g_cursor[N_NODES];
__device__ __align__(8) int2 g_csr_edge[N_EDGES];   // {src, norm bits}
__device__ int   g_total;

// ---------------- degree / normalization / CSR -----------------------------
__global__ void k_deg_zero() {
    int i = blockIdx.x * blockDim.x + threadIdx.x;
    if (i < N_NODES) g_deg[i] = 0;
    if (i == 0) g_total = 0;
}

__global__ void k_deg_count(const int* __restrict__ ei) {
    int e = blockIdx.x * blockDim.x + threadIdx.x;
    if (e < N_EDGES) atomicAdd(&g_deg[ei[N_EDGES + e]], 1);
}

// block-parallel range allocation: one atomicAdd per block; range ORDER is
// irrelevant (CSR fill order is already arbitrary). Also computes dinv.
__global__ void __launch_bounds__(1024) k_rowstart() {
    int i    = blockIdx.x * 1024 + threadIdx.x;
    int lane = threadIdx.x & 31;
    int wid  = threadIdx.x >> 5;
    int deg  = (i < N_NODES) ? g_deg[i] : 0;

    int v = deg;
#pragma unroll
    for (int off = 1; off < 32; off <<= 1) {
        int t = __shfl_up_sync(0xffffffffu, v, off);
        if (lane >= off) v += t;
    }
    __shared__ int wsum[32];
    __shared__ int base;
    if (lane == 31) wsum[wid] = v;
    __syncthreads();
    if (wid == 0) {
        int wv = wsum[lane];
#pragma unroll
        for (int off = 1; off < 32; off <<= 1) {
            int t = __shfl_up_sync(0xffffffffu, wv, off);
            if (lane >= off) wv += t;
        }
        wsum[lane] = wv;
        if (lane == 31) base = atomicAdd(&g_total, wv);
    }
    __syncthreads();
    int excl = base + (wid > 0 ? wsum[wid - 1] : 0) + v - deg;
    if (i < N_NODES) {
        g_rowstart[i] = excl;
        g_cursor[i]   = excl;
        g_dinv[i]     = rsqrtf((float)(deg + 1));   // +1 self loop
    }
}

__global__ void k_csr_fill(const int* __restrict__ ei) {
    int e = blockIdx.x * blockDim.x + threadIdx.x;
    if (e >= N_EDGES) return;
    int s = ei[e];
    int d = ei[N_EDGES + e];
    int pos = atomicAdd(&g_cursor[d], 1);
    g_csr_edge[pos] = make_int2(s, __float_as_int(g_dinv[s] * g_dinv[d]));
}

// ---------------- GEMM: Y[n,NCOL] = X[n,128] @ W[128,NCOL] (+bias) ---------
// R4 design (proven): 32-row blocks, 256 threads, f32x2 FMAs; fma pipe is the
// binder. HALF_OUT additionally writes an fp16 copy for the aggregate gather.
template <int NCOL, bool BIAS, bool HALF_OUT>
__global__ void __launch_bounds__(256) k_gemm(
    const float* __restrict__ X, const float* __restrict__ W,
    const float* __restrict__ bias, float* __restrict__ Y,
    __half* __restrict__ Yh, int nrows)
{
    constexpr int CG  = NCOL / 4;     // float4 column groups (32 or 16)
    constexpr int RG  = 256 / CG;     // row groups (8 or 16)
    constexpr int RPT = 32 / RG;      // rows per thread (4 or 2)

    __shared__ float Ws[64 * NCOL];
    __shared__ float Xs[32 * 68];

    const int tid  = threadIdx.x;
    const int cg   = tid % CG;
    const int rg   = tid / CG;
    const int row0 = blockIdx.x * 32;

    u64 accL[RPT], accH[RPT];
#pragma unroll
    for (int r = 0; r < RPT; ++r) { accL[r] = 0ull; accH[r] = 0ull; }

    for (int kt = 0; kt < 2; ++kt) {
        const float4* Wg  = (const float4*)(W + (size_t)kt * 64 * NCOL);
        float4*       Ws4 = (float4*)Ws;
#pragma unroll 4
        for (int i = tid; i < 64 * NCOL / 4; i += 256) Ws4[i] = Wg[i];

        for (int i = tid; i < 32 * 16; i += 256) {
            int r  = i / 16;
            int kk = i % 16;
            float4 v = make_float4(0.f, 0.f, 0.f, 0.f);
            if (row0 + r < nrows)
                v = ((const float4*)(X + (size_t)(row0 + r) * DIM + kt * 64))[kk];
            ((float4*)(Xs + r * 68))[kk] = v;
        }
        __syncthreads();

#pragma unroll 8
        for (int k = 0; k < 64; ++k) {
            ulonglong2 w = *((const ulonglong2*)(Ws + k * NCOL) + cg);
#pragma unroll
            for (int r = 0; r < RPT; ++r) {
                unsigned xu = __float_as_uint(Xs[(rg * RPT + r) * 68 + k]);
                u64 xp;
                asm("mov.b64 %0, {%1, %1};" : "=l"(xp) : "r"(xu));
                asm("fma.rn.f32x2 %0, %1, %2, %0;" : "+l"(accL[r]) : "l"(xp), "l"(w.x));
                asm("fma.rn.f32x2 %0, %1, %2, %0;" : "+l"(accH[r]) : "l"(xp), "l"(w.y));
            }
        }
        __syncthreads();
    }

#pragma unroll
    for (int r = 0; r < RPT; ++r) {
        int row = row0 + rg * RPT + r;
        if (row < nrows) {
            float2 lo, hi;
            asm("mov.b64 {%0, %1}, %2;" : "=f"(lo.x), "=f"(lo.y) : "l"(accL[r]));
            asm("mov.b64 {%0, %1}, %2;" : "=f"(hi.x), "=f"(hi.y) : "l"(accH[r]));
            float4 o = make_float4(lo.x, lo.y, hi.x, hi.y);
            if (BIAS) {
                float4 b = ((const float4*)bias)[cg];
                o.x += b.x; o.y += b.y; o.z += b.z; o.w += b.w;
            }
            ((float4*)(Y + (size_t)row * NCOL))[cg] = o;
            if (HALF_OUT) {
                __half2 h0 = __floats2half2_rn(o.x, o.y);
                __half2 h1 = __floats2half2_rn(o.z, o.w);
                uint2 pk;
                __builtin_memcpy(&pk.x, &h0, 4);
                __builtin_memcpy(&pk.y, &h1, 4);
                ((uint2*)(Yh + (size_t)row * NCOL))[cg] = pk;
            }
        }
    }
}

// ---------------- CSR aggregation + self-loop + bias + relu ----------------
// warp per node; messages gathered in fp16 (half L2 traffic), accumulated in
// fp32; self-loop term taken from the exact fp32 buffer. 2x unroll ONLY
// (4x overflows the L1tex wavefront queue at occ~8; measured +30us in R6).
__global__ void __launch_bounds__(256) k_aggregate(
    const float* __restrict__ A, const __half* __restrict__ Ah,
    float* __restrict__ B, const float* __restrict__ bias)
{
    int node = (blockIdx.x * 256 + threadIdx.x) >> 5;
    int lane = threadIdx.x & 31;
    if (node >= N_NODES) return;

    const uint2* AH = (const uint2*)Ah;     // 32 uint2 per 128-half row
    int beg = g_rowstart[node];
    int cnt = g_deg[node];

    float4 acc0 = make_float4(0.f, 0.f, 0.f, 0.f);
    float4 acc1 = make_float4(0.f, 0.f, 0.f, 0.f);

    int j = 0;
    for (; j + 2 <= cnt; j += 2) {
        int2 e0 = g_csr_edge[beg + j];
        int2 e1 = g_csr_edge[beg + j + 1];
        float n0 = __int_as_float(e0.y);
        float n1 = __int_as_float(e1.y);
        uint2 r0 = AH[(size_t)e0.x * 32 + lane];
        uint2 r1 = AH[(size_t)e1.x * 32 + lane];
        __half2 h; float2 f;
        __builtin_memcpy(&h, &r0.x, 4); f = __half22float2(h);
        acc0.x += f.x * n0; acc0.y += f.y * n0;
        __builtin_memcpy(&h, &r0.y, 4); f = __half22float2(h);
        acc0.z += f.x * n0; acc0.w += f.y * n0;
        __builtin_memcpy(&h, &r1.x, 4); f = __half22float2(h);
        acc1.x += f.x * n1; acc1.y += f.y * n1;
        __builtin_memcpy(&h, &r1.y, 4); f = __half22float2(h);
        acc1.z += f.x * n1; acc1.w += f.y * n1;
    }
    if (j < cnt) {
        int2 e0 = g_csr_edge[beg + j];
        float n0 = __int_as_float(e0.y);
        uint2 r0 = AH[(size_t)e0.x * 32 + lane];
        __half2 h; float2 f;
        __builtin_memcpy(&h, &r0.x, 4); f = __half22float2(h);
        acc0.x += f.x * n0; acc0.y += f.y * n0;
        __builtin_memcpy(&h, &r0.y, 4); f = __half22float2(h);
        acc0.z += f.x * n0; acc0.w += f.y * n0;
    }

    float di = g_dinv[node];
    float sn = di * di;
    float4 self = ((const float4*)A)[(size_t)node * 32 + lane];
    float4 bb   = ((const float4*)bias)[lane];
    float4 o;
    o.x = fmaxf(acc0.x + acc1.x + self.x * sn + bb.x, 0.f);
    o.y = fmaxf(acc0.y + acc1.y + self.y * sn + bb.y, 0.f);
    o.z = fmaxf(acc0.z + acc1.z + self.z * sn + bb.z, 0.f);
    o.w = fmaxf(acc0.w + acc1.w + self.w * sn + bb.w, 0.f);
    ((float4*)(B + (size_t)node * DIM))[lane] = o;
}

// ---------------- launch ----------------------------------------------------
extern "C" void kernel_launch(void* const* d_in, const int* in_sizes, int n_in,
                              void* d_out, int out_size)
{
    const float* x    = (const float*)d_in[0];
    const int*   ei   = (const int*)d_in[1];     // int32 (JAX x64 disabled)
    const float* W1   = (const float*)d_in[2];
    const float* b1   = (const float*)d_in[3];
    const float* W2   = (const float*)d_in[4];
    const float* b2   = (const float*)d_in[5];
    const float* fcW  = (const float*)d_in[6];
    const float* fcb  = (const float*)d_in[7];
    float*       out  = (float*)d_out;

    void *pA_, *pB_, *pH_;
    cudaGetSymbolAddress(&pA_, g_bufA);
    cudaGetSymbolAddress(&pB_, g_bufB);
    cudaGetSymbolAddress(&pH_, g_bufH);
    float*  bufA = (float*)pA_;
    float*  bufB = (float*)pB_;
    __half* bufH = (__half*)pH_;

    const int TB = 256;
    const int gN  = (N_NODES + TB - 1) / TB;
    const int gE  = (N_EDGES + TB - 1) / TB;
    const int gG  = (N_NODES + 31) / 32;            // 32-row gemm tiles
    const int gAg = (N_NODES * 32 + TB - 1) / TB;   // warp per node
    const int gRS = (N_NODES + 1023) / 1024;

    // CSR precompute
    k_deg_zero<<<gN, TB>>>();
    k_deg_count<<<gE, TB>>>(ei);
    k_rowstart<<<gRS, 1024>>>();
    k_csr_fill<<<gE, TB>>>(ei);

    // layer 1
    k_gemm<DIM, false, true><<<gG, TB>>>(x, W1, nullptr, bufA, bufH, N_NODES);
    k_aggregate<<<gAg, TB>>>(bufA, bufH, bufB, b1);

    // layer 2
    k_gemm<DIM, false, true><<<gG, TB>>>(bufB, W2, nullptr, bufA, bufH, N_NODES);
    k_aggregate<<<gAg, TB>>>(bufA, bufH, bufB, b2);

    // fc
    k_gemm<DOUT, true, false><<<gG, TB>>>(bufB, fcW, fcb, out, nullptr, N_NODES);
}

// round 10
// speedup vs baseline: 1.2182x; 1.0880x over previous
#include <cuda_runtime.h>
#include <cuda_fp16.h>
#include <cstddef>
#include <cstdint>

#define N_NODES 100000
#define N_EDGES 1600000
#define DIM     128
#define DOUT    64

typedef unsigned long long u64;

// ---------------- scratch (device globals; no allocation allowed) ----------
__device__ __align__(16) float  g_bufB[(size_t)N_NODES * DIM];   // fp32 activations
__device__ __align__(16) __half g_bufH[(size_t)N_NODES * DIM];   // fp16 messages
__device__ float g_dinv[N_NODES];
__device__ int   g_deg[N_NODES];
__device__ int   g_rowstart[N_NODES];
__device__ int   g_cursor[N_NODES];
__device__ __align__(8) int2 g_csr_edge[N_EDGES];   // {src, norm bits}
__device__ int   g_total;

// ---------------- degree / normalization / CSR -----------------------------
__global__ void k_deg_zero() {
    int i = blockIdx.x * blockDim.x + threadIdx.x;
    if (i < N_NODES) g_deg[i] = 0;
    if (i == 0) g_total = 0;
}

__global__ void k_deg_count(const int* __restrict__ ei) {
    int e = blockIdx.x * blockDim.x + threadIdx.x;
    if (e < N_EDGES) atomicAdd(&g_deg[ei[N_EDGES + e]], 1);
}

// block-parallel range allocation: one atomicAdd per block; range ORDER is
// irrelevant (CSR fill order is already arbitrary). Also computes dinv.
__global__ void __launch_bounds__(1024) k_rowstart() {
    int i    = blockIdx.x * 1024 + threadIdx.x;
    int lane = threadIdx.x & 31;
    int wid  = threadIdx.x >> 5;
    int deg  = (i < N_NODES) ? g_deg[i] : 0;

    int v = deg;
#pragma unroll
    for (int off = 1; off < 32; off <<= 1) {
        int t = __shfl_up_sync(0xffffffffu, v, off);
        if (lane >= off) v += t;
    }
    __shared__ int wsum[32];
    __shared__ int base;
    if (lane == 31) wsum[wid] = v;
    __syncthreads();
    if (wid == 0) {
        int wv = wsum[lane];
#pragma unroll
        for (int off = 1; off < 32; off <<= 1) {
            int t = __shfl_up_sync(0xffffffffu, wv, off);
            if (lane >= off) wv += t;
        }
        wsum[lane] = wv;
        if (lane == 31) base = atomicAdd(&g_total, wv);
    }
    __syncthreads();
    int excl = base + (wid > 0 ? wsum[wid - 1] : 0) + v - deg;
    if (i < N_NODES) {
        g_rowstart[i] = excl;
        g_cursor[i]   = excl;
        g_dinv[i]     = rsqrtf((float)(deg + 1));   // +1 self loop
    }
}

__global__ void k_csr_fill(const int* __restrict__ ei) {
    int e = blockIdx.x * blockDim.x + threadIdx.x;
    if (e >= N_EDGES) return;
    int s = ei[e];
    int d = ei[N_EDGES + e];
    int pos = atomicAdd(&g_cursor[d], 1);
    g_csr_edge[pos] = make_int2(s, __float_as_int(g_dinv[s] * g_dinv[d]));
}

// ---------------- GEMM: Y[n,NCOL] = X[n,128] @ W[128,NCOL] (+bias) ---------
// R4 design (proven): 32-row blocks, 256 threads, f32x2 FMAs; fma pipe is the
// binder. OUT_MODE: 0 = fp32 only (fc), 1 = fp16 only (layer GEMMs).
template <int NCOL, bool BIAS, int OUT_MODE>
__global__ void __launch_bounds__(256) k_gemm(
    const float* __restrict__ X, const float* __restrict__ W,
    const float* __restrict__ bias, float* __restrict__ Y,
    __half* __restrict__ Yh, int nrows)
{
    constexpr int CG  = NCOL / 4;     // float4 column groups (32 or 16)
    constexpr int RG  = 256 / CG;     // row groups (8 or 16)
    constexpr int RPT = 32 / RG;      // rows per thread (4 or 2)

    __shared__ float Ws[64 * NCOL];
    __shared__ float Xs[32 * 68];

    const int tid  = threadIdx.x;
    const int cg   = tid % CG;
    const int rg   = tid / CG;
    const int row0 = blockIdx.x * 32;

    u64 accL[RPT], accH[RPT];
#pragma unroll
    for (int r = 0; r < RPT; ++r) { accL[r] = 0ull; accH[r] = 0ull; }

    for (int kt = 0; kt < 2; ++kt) {
        const float4* Wg  = (const float4*)(W + (size_t)kt * 64 * NCOL);
        float4*       Ws4 = (float4*)Ws;
#pragma unroll 4
        for (int i = tid; i < 64 * NCOL / 4; i += 256) Ws4[i] = Wg[i];

        for (int i = tid; i < 32 * 16; i += 256) {
            int r  = i / 16;
            int kk = i % 16;
            float4 v = make_float4(0.f, 0.f, 0.f, 0.f);
            if (row0 + r < nrows)
                v = ((const float4*)(X + (size_t)(row0 + r) * DIM + kt * 64))[kk];
            ((float4*)(Xs + r * 68))[kk] = v;
        }
        __syncthreads();

#pragma unroll 8
        for (int k = 0; k < 64; ++k) {
            ulonglong2 w = *((const ulonglong2*)(Ws + k * NCOL) + cg);
#pragma unroll
            for (int r = 0; r < RPT; ++r) {
                unsigned xu = __float_as_uint(Xs[(rg * RPT + r) * 68 + k]);
                u64 xp;
                asm("mov.b64 %0, {%1, %1};" : "=l"(xp) : "r"(xu));
                asm("fma.rn.f32x2 %0, %1, %2, %0;" : "+l"(accL[r]) : "l"(xp), "l"(w.x));
                asm("fma.rn.f32x2 %0, %1, %2, %0;" : "+l"(accH[r]) : "l"(xp), "l"(w.y));
            }
        }
        __syncthreads();
    }

#pragma unroll
    for (int r = 0; r < RPT; ++r) {
        int row = row0 + rg * RPT + r;
        if (row < nrows) {
            float2 lo, hi;
            asm("mov.b64 {%0, %1}, %2;" : "=f"(lo.x), "=f"(lo.y) : "l"(accL[r]));
            asm("mov.b64 {%0, %1}, %2;" : "=f"(hi.x), "=f"(hi.y) : "l"(accH[r]));
            float4 o = make_float4(lo.x, lo.y, hi.x, hi.y);
            if (BIAS) {
                float4 b = ((const float4*)bias)[cg];
                o.x += b.x; o.y += b.y; o.z += b.z; o.w += b.w;
            }
            if (OUT_MODE == 0) {
                ((float4*)(Y + (size_t)row * NCOL))[cg] = o;
            } else {
                __half2 h0 = __floats2half2_rn(o.x, o.y);
                __half2 h1 = __floats2half2_rn(o.z, o.w);
                uint2 pk;
                __builtin_memcpy(&pk.x, &h0, 4);
                __builtin_memcpy(&pk.y, &h1, 4);
                ((uint2*)(Yh + (size_t)row * NCOL))[cg] = pk;
            }
        }
    }
}

// fp16x2 pair -> fp32 accumulate helper
__device__ __forceinline__ void acc_h2(float4& a, uint2 r, float n) {
    __half2 h; float2 f;
    __builtin_memcpy(&h, &r.x, 4); f = __half22float2(h);
    a.x += f.x * n; a.y += f.y * n;
    __builtin_memcpy(&h, &r.y, 4); f = __half22float2(h);
    a.z += f.x * n; a.w += f.y * n;
}

// ---------------- CSR aggregation + self-loop + bias + relu ----------------
// warp per node; fp16 gathers, fp32 accumulation, fp32 output.
// 4x unroll on fp16 = 8 in-flight 128B lines per warp, the same L1tex queue
// footprint as the proven fp32 2x config (R6 lesson is about lines, not MLP).
__global__ void __launch_bounds__(256) k_aggregate(
    const __half* __restrict__ Ah, float* __restrict__ B,
    const float* __restrict__ bias)
{
    int node = (blockIdx.x * 256 + threadIdx.x) >> 5;
    int lane = threadIdx.x & 31;
    if (node >= N_NODES) return;

    const uint2* AH = (const uint2*)Ah;     // 32 uint2 per 128-half row
    int beg = g_rowstart[node];
    int cnt = g_deg[node];

    float4 acc0 = make_float4(0.f, 0.f, 0.f, 0.f);
    float4 acc1 = make_float4(0.f, 0.f, 0.f, 0.f);

    int j = 0;
    for (; j + 4 <= cnt; j += 4) {
        int2 e0 = g_csr_edge[beg + j + 0];
        int2 e1 = g_csr_edge[beg + j + 1];
        int2 e2 = g_csr_edge[beg + j + 2];
        int2 e3 = g_csr_edge[beg + j + 3];
        uint2 r0 = AH[(size_t)e0.x * 32 + lane];
        uint2 r1 = AH[(size_t)e1.x * 32 + lane];
        uint2 r2 = AH[(size_t)e2.x * 32 + lane];
        uint2 r3 = AH[(size_t)e3.x * 32 + lane];
        acc_h2(acc0, r0, __int_as_float(e0.y));
        acc_h2(acc1, r1, __int_as_float(e1.y));
        acc_h2(acc0, r2, __int_as_float(e2.y));
        acc_h2(acc1, r3, __int_as_float(e3.y));
    }
    for (; j < cnt; ++j) {
        int2 e0 = g_csr_edge[beg + j];
        uint2 r0 = AH[(size_t)e0.x * 32 + lane];
        acc_h2(acc0, r0, __int_as_float(e0.y));
    }

    float di = g_dinv[node];
    float sn = di * di;
    uint2 sr = AH[(size_t)node * 32 + lane];
    acc_h2(acc1, sr, sn);                       // self loop from fp16 row
    float4 bb = ((const float4*)bias)[lane];
    float4 o;
    o.x = fmaxf(acc0.x + acc1.x + bb.x, 0.f);
    o.y = fmaxf(acc0.y + acc1.y + bb.y, 0.f);
    o.z = fmaxf(acc0.z + acc1.z + bb.z, 0.f);
    o.w = fmaxf(acc0.w + acc1.w + bb.w, 0.f);
    ((float4*)(B + (size_t)node * DIM))[lane] = o;
}

// ---------------- launch ----------------------------------------------------
extern "C" void kernel_launch(void* const* d_in, const int* in_sizes, int n_in,
                              void* d_out, int out_size)
{
    const float* x    = (const float*)d_in[0];
    const int*   ei   = (const int*)d_in[1];     // int32 (JAX x64 disabled)
    const float* W1   = (const float*)d_in[2];
    const float* b1   = (const float*)d_in[3];
    const float* W2   = (const float*)d_in[4];
    const float* b2   = (const float*)d_in[5];
    const float* fcW  = (const float*)d_in[6];
    const float* fcb  = (const float*)d_in[7];
    float*       out  = (float*)d_out;

    void *pB_, *pH_;
    cudaGetSymbolAddress(&pB_, g_bufB);
    cudaGetSymbolAddress(&pH_, g_bufH);
    float*  bufB = (float*)pB_;
    __half* bufH = (__half*)pH_;

    const int TB = 256;
    const int gN  = (N_NODES + TB - 1) / TB;
    const int gE  = (N_EDGES + TB - 1) / TB;
    const int gG  = (N_NODES + 31) / 32;            // 32-row gemm tiles
    const int gAg = (N_NODES * 32 + TB - 1) / TB;   // warp per node
    const int gRS = (N_NODES + 1023) / 1024;

    // CSR precompute
    k_deg_zero<<<gN, TB>>>();
    k_deg_count<<<gE, TB>>>(ei);
    k_rowstart<<<gRS, 1024>>>();
    k_csr_fill<<<gE, TB>>>(ei);

    // layer 1: fp16 messages only
    k_gemm<DIM, false, 1><<<gG, TB>>>(x, W1, nullptr, nullptr, bufH, N_NODES);
    k_aggregate<<<gAg, TB>>>(bufH, bufB, b1);

    // layer 2
    k_gemm<DIM, false, 1><<<gG, TB>>>(bufB, W2, nullptr, nullptr, bufH, N_NODES);
    k_aggregate<<<gAg, TB>>>(bufH, bufB, b2);

    // fc (fp32 exact)
    k_gemm<DOUT, true, 0><<<gG, TB>>>(bufB, fcW, fcb, out, nullptr, N_NODES);
}

// round 11
// speedup vs baseline: 1.2340x; 1.0130x over previous
#include <cuda_runtime.h>
#include <cuda_fp16.h>
#include <cstddef>
#include <cstdint>

#define N_NODES 100000
#define N_EDGES 1600000
#define DIM     128
#define DOUT    64

typedef unsigned long long u64;

// ---------------- scratch (device globals; no allocation allowed) ----------
__device__ __align__(16) float  g_bufB[(size_t)N_NODES * DIM];   // fp32 activations
__device__ __align__(16) __half g_bufH[(size_t)N_NODES * DIM];   // fp16 messages
__device__ float g_dinv[N_NODES];
__device__ int   g_deg[N_NODES];
__device__ int   g_rowstart[N_NODES];
__device__ int   g_cursor[N_NODES];
__device__ __align__(8) int2 g_csr_edge[N_EDGES];   // {src, norm bits}
__device__ int   g_total;

// ---------------- degree / normalization / CSR -----------------------------
__global__ void k_deg_zero() {
    int i = blockIdx.x * blockDim.x + threadIdx.x;
    if (i < N_NODES) g_deg[i] = 0;
    if (i == 0) g_total = 0;
}

__global__ void k_deg_count(const int* __restrict__ ei) {
    int e = blockIdx.x * blockDim.x + threadIdx.x;
    if (e < N_EDGES) atomicAdd(&g_deg[ei[N_EDGES + e]], 1);
}

// block-parallel range allocation: one atomicAdd per block; range ORDER is
// irrelevant (CSR fill order is already arbitrary). Also computes dinv.
__global__ void __launch_bounds__(1024) k_rowstart() {
    int i    = blockIdx.x * 1024 + threadIdx.x;
    int lane = threadIdx.x & 31;
    int wid  = threadIdx.x >> 5;
    int deg  = (i < N_NODES) ? g_deg[i] : 0;

    int v = deg;
#pragma unroll
    for (int off = 1; off < 32; off <<= 1) {
        int t = __shfl_up_sync(0xffffffffu, v, off);
        if (lane >= off) v += t;
    }
    __shared__ int wsum[32];
    __shared__ int base;
    if (lane == 31) wsum[wid] = v;
    __syncthreads();
    if (wid == 0) {
        int wv = wsum[lane];
#pragma unroll
        for (int off = 1; off < 32; off <<= 1) {
            int t = __shfl_up_sync(0xffffffffu, wv, off);
            if (lane >= off) wv += t;
        }
        wsum[lane] = wv;
        if (lane == 31) base = atomicAdd(&g_total, wv);
    }
    __syncthreads();
    int excl = base + (wid > 0 ? wsum[wid - 1] : 0) + v - deg;
    if (i < N_NODES) {
        g_rowstart[i] = excl;
        g_cursor[i]   = excl;
        g_dinv[i]     = rsqrtf((float)(deg + 1));   // +1 self loop
    }
}

__global__ void k_csr_fill(const int* __restrict__ ei) {
    int e = blockIdx.x * blockDim.x + threadIdx.x;
    if (e >= N_EDGES) return;
    int s = ei[e];
    int d = ei[N_EDGES + e];
    int pos = atomicAdd(&g_cursor[d], 1);
    g_csr_edge[pos] = make_int2(s, __float_as_int(g_dinv[s] * g_dinv[d]));
}

// ---------------- GEMM: Y[n,NCOL] = X[n,128] @ W[128,NCOL] (+bias) ---------
// R4 design (proven): 32-row blocks, 256 threads, f32x2 FMAs; fma pipe is the
// binder. OUT_MODE: 0 = fp32 only (fc), 1 = fp16 only (layer GEMMs).
template <int NCOL, bool BIAS, int OUT_MODE>
__global__ void __launch_bounds__(256) k_gemm(
    const float* __restrict__ X, const float* __restrict__ W,
    const float* __restrict__ bias, float* __restrict__ Y,
    __half* __restrict__ Yh, int nrows)
{
    constexpr int CG  = NCOL / 4;     // float4 column groups (32 or 16)
    constexpr int RG  = 256 / CG;     // row groups (8 or 16)
    constexpr int RPT = 32 / RG;      // rows per thread (4 or 2)

    __shared__ float Ws[64 * NCOL];
    __shared__ float Xs[32 * 68];

    const int tid  = threadIdx.x;
    const int cg   = tid % CG;
    const int rg   = tid / CG;
    const int row0 = blockIdx.x * 32;

    u64 accL[RPT], accH[RPT];
#pragma unroll
    for (int r = 0; r < RPT; ++r) { accL[r] = 0ull; accH[r] = 0ull; }

    for (int kt = 0; kt < 2; ++kt) {
        const float4* Wg  = (const float4*)(W + (size_t)kt * 64 * NCOL);
        float4*       Ws4 = (float4*)Ws;
#pragma unroll 4
        for (int i = tid; i < 64 * NCOL / 4; i += 256) Ws4[i] = Wg[i];

        for (int i = tid; i < 32 * 16; i += 256) {
            int r  = i / 16;
            int kk = i % 16;
            float4 v = make_float4(0.f, 0.f, 0.f, 0.f);
            if (row0 + r < nrows)
                v = ((const float4*)(X + (size_t)(row0 + r) * DIM + kt * 64))[kk];
            ((float4*)(Xs + r * 68))[kk] = v;
        }
        __syncthreads();

#pragma unroll 8
        for (int k = 0; k < 64; ++k) {
            ulonglong2 w = *((const ulonglong2*)(Ws + k * NCOL) + cg);
#pragma unroll
            for (int r = 0; r < RPT; ++r) {
                unsigned xu = __float_as_uint(Xs[(rg * RPT + r) * 68 + k]);
                u64 xp;
                asm("mov.b64 %0, {%1, %1};" : "=l"(xp) : "r"(xu));
                asm("fma.rn.f32x2 %0, %1, %2, %0;" : "+l"(accL[r]) : "l"(xp), "l"(w.x));
                asm("fma.rn.f32x2 %0, %1, %2, %0;" : "+l"(accH[r]) : "l"(xp), "l"(w.y));
            }
        }
        __syncthreads();
    }

#pragma unroll
    for (int r = 0; r < RPT; ++r) {
        int row = row0 + rg * RPT + r;
        if (row < nrows) {
            float2 lo, hi;
            asm("mov.b64 {%0, %1}, %2;" : "=f"(lo.x), "=f"(lo.y) : "l"(accL[r]));
            asm("mov.b64 {%0, %1}, %2;" : "=f"(hi.x), "=f"(hi.y) : "l"(accH[r]));
            float4 o = make_float4(lo.x, lo.y, hi.x, hi.y);
            if (BIAS) {
                float4 b = ((const float4*)bias)[cg];
                o.x += b.x; o.y += b.y; o.z += b.z; o.w += b.w;
            }
            if (OUT_MODE == 0) {
                ((float4*)(Y + (size_t)row * NCOL))[cg] = o;
            } else {
                __half2 h0 = __floats2half2_rn(o.x, o.y);
                __half2 h1 = __floats2half2_rn(o.z, o.w);
                uint2 pk;
                __builtin_memcpy(&pk.x, &h0, 4);
                __builtin_memcpy(&pk.y, &h1, 4);
                ((uint2*)(Yh + (size_t)row * NCOL))[cg] = pk;
            }
        }
    }
}

// fp16x2 pair -> fp32 accumulate helper
__device__ __forceinline__ void acc_h2(float4& a, uint2 r, float n) {
    __half2 h; float2 f;
    __builtin_memcpy(&h, &r.x, 4); f = __half22float2(h);
    a.x += f.x * n; a.y += f.y * n;
    __builtin_memcpy(&h, &r.y, 4); f = __half22float2(h);
    a.z += f.x * n; a.w += f.y * n;
}

// ---------------- CSR aggregation + self-loop + bias + relu ----------------
// warp per node; fp16 gathers, fp32 accumulation, fp32 output.
// 4x unroll on fp16 = 8 in-flight 128B lines per warp (same L1tex queue
// footprint as the proven fp32 2x config; the R6 lesson is lines, not MLP).
__global__ void __launch_bounds__(256) k_aggregate(
    const __half* __restrict__ Ah, float* __restrict__ B,
    const float* __restrict__ bias)
{
    int node = (blockIdx.x * 256 + threadIdx.x) >> 5;
    int lane = threadIdx.x & 31;
    if (node >= N_NODES) return;

    const uint2* AH = (const uint2*)Ah;     // 32 uint2 per 128-half row
    int beg = g_rowstart[node];
    int cnt = g_deg[node];

    float4 acc0 = make_float4(0.f, 0.f, 0.f, 0.f);
    float4 acc1 = make_float4(0.f, 0.f, 0.f, 0.f);

    int j = 0;
    for (; j + 4 <= cnt; j += 4) {
        int2 e0 = g_csr_edge[beg + j + 0];
        int2 e1 = g_csr_edge[beg + j + 1];
        int2 e2 = g_csr_edge[beg + j + 2];
        int2 e3 = g_csr_edge[beg + j + 3];
        uint2 r0 = AH[(size_t)e0.x * 32 + lane];
        uint2 r1 = AH[(size_t)e1.x * 32 + lane];
        uint2 r2 = AH[(size_t)e2.x * 32 + lane];
        uint2 r3 = AH[(size_t)e3.x * 32 + lane];
        acc_h2(acc0, r0, __int_as_float(e0.y));
        acc_h2(acc1, r1, __int_as_float(e1.y));
        acc_h2(acc0, r2, __int_as_float(e2.y));
        acc_h2(acc1, r3, __int_as_float(e3.y));
    }
    for (; j < cnt; ++j) {
        int2 e0 = g_csr_edge[beg + j];
        uint2 r0 = AH[(size_t)e0.x * 32 + lane];
        acc_h2(acc0, r0, __int_as_float(e0.y));
    }

    float di = g_dinv[node];
    float sn = di * di;
    uint2 sr = AH[(size_t)node * 32 + lane];
    acc_h2(acc1, sr, sn);                       // self loop from fp16 row
    float4 bb = ((const float4*)bias)[lane];
    float4 o;
    o.x = fmaxf(acc0.x + acc1.x + bb.x, 0.f);
    o.y = fmaxf(acc0.y + acc1.y + bb.y, 0.f);
    o.z = fmaxf(acc0.z + acc1.z + bb.z, 0.f);
    o.w = fmaxf(acc0.w + acc1.w + bb.w, 0.f);
    ((float4*)(B + (size_t)node * DIM))[lane] = o;
}

// ---------------- launch ----------------------------------------------------
extern "C" void kernel_launch(void* const* d_in, const int* in_sizes, int n_in,
                              void* d_out, int out_size)
{
    const float* x    = (const float*)d_in[0];
    const int*   ei   = (const int*)d_in[1];     // int32 (JAX x64 disabled)
    const float* W1   = (const float*)d_in[2];
    const float* b1   = (const float*)d_in[3];
    const float* W2   = (const float*)d_in[4];
    const float* b2   = (const float*)d_in[5];
    const float* fcW  = (const float*)d_in[6];
    const float* fcb  = (const float*)d_in[7];
    float*       out  = (float*)d_out;

    void *pB_, *pH_;
    cudaGetSymbolAddress(&pB_, g_bufB);
    cudaGetSymbolAddress(&pH_, g_bufH);
    float*  bufB = (float*)pB_;
    __half* bufH = (__half*)pH_;

    const int TB = 256;
    const int gN  = (N_NODES + TB - 1) / TB;
    const int gE  = (N_EDGES + TB - 1) / TB;
    const int gG  = (N_NODES + 31) / 32;            // 32-row gemm tiles
    const int gAg = (N_NODES * 32 + TB - 1) / TB;   // warp per node
    const int gRS = (N_NODES + 1023) / 1024;

    // fork a side stream: CSR precompute runs concurrently with GEMM1
    // (host-side stream/event create/destroy: no device allocation, done
    // identically every call; record/wait edges are graph-capture legal)
    cudaStream_t sCsr;
    cudaStreamCreateWithFlags(&sCsr, cudaStreamNonBlocking);
    cudaEvent_t evFork, evCsrDone;
    cudaEventCreateWithFlags(&evFork,    cudaEventDisableTiming);
    cudaEventCreateWithFlags(&evCsrDone, cudaEventDisableTiming);

    cudaEventRecord(evFork, 0);
    cudaStreamWaitEvent(sCsr, evFork, 0);

    // CSR precompute chain (side stream)
    k_deg_zero<<<gN, TB, 0, sCsr>>>();
    k_deg_count<<<gE, TB, 0, sCsr>>>(ei);
    k_rowstart<<<gRS, 1024, 0, sCsr>>>();
    k_csr_fill<<<gE, TB, 0, sCsr>>>(ei);
    cudaEventRecord(evCsrDone, sCsr);

    // GEMM1 (main stream, concurrent with CSR build)
    k_gemm<DIM, false, 1><<<gG, TB>>>(x, W1, nullptr, nullptr, bufH, N_NODES);

    // join: aggregate1 needs both GEMM1 output and CSR
    cudaStreamWaitEvent(0, evCsrDone, 0);
    k_aggregate<<<gAg, TB>>>(bufH, bufB, b1);

    // layer 2
    k_gemm<DIM, false, 1><<<gG, TB>>>(bufB, W2, nullptr, nullptr, bufH, N_NODES);
    k_aggregate<<<gAg, TB>>>(bufH, bufB, b2);

    // fc (fp32 exact)
    k_gemm<DOUT, true, 0><<<gG, TB>>>(bufB, fcW, fcb, out, nullptr, N_NODES);

    cudaEventDestroy(evFork);
    cudaEventDestroy(evCsrDone);
    cudaStreamDestroy(sCsr);
}